// round 1
// baseline (speedup 1.0000x reference)
#include <cuda_runtime.h>
#include <cstdint>

// Problem constants
constexpr int Bc  = 2;
constexpr int Sc  = 4096;
constexpr int DMc = 768;
constexpr int Hc  = 12;
constexpr int HDc = 64;
constexpr int BSc = Bc * Sc;          // 8192 rows
constexpr int BHc = Bc * Hc;          // 24

// Device scratch (allocation-free contract: static __device__ arrays)
__device__ float g_q[(size_t)BHc * Sc * HDc];
__device__ float g_k[(size_t)BHc * Sc * HDc];
__device__ float g_v[(size_t)BHc * Sc * HDc];
__device__ float g_attn[(size_t)BSc * DMc];
__device__ float g_res[(size_t)BSc * DMc];

// ---------------------------------------------------------------------------
// QKV projection GEMM: out[m][n] = sum_k X[m][k] * W[n][k] + bias[n]
// Tile 64x64, K-chunk 16, 256 threads, 4x4 micro-tile per thread.
// Epilogue: RoPE (for q,k) via shfl partner exchange, write [B,H,S,HD].
// which: 0=q (rope), 1=k (rope), 2=v (no rope)
// ---------------------------------------------------------------------------
__global__ __launch_bounds__(256) void gemm_proj(
    const float* __restrict__ X, const float* __restrict__ W,
    const float* __restrict__ bias,
    const float* __restrict__ cosb, const float* __restrict__ sinb,
    int which)
{
    __shared__ float As[64][16];
    __shared__ float Bs[16][68];   // k-major, padded: conflict-free float4 reads

    const int tid = threadIdx.x;
    const int ty = tid >> 4, tx = tid & 15;
    const int n0 = blockIdx.x * 64;
    const int m0 = blockIdx.y * 64;

    const int lrow = tid >> 2, lkq = tid & 3;

    float acc[4][4] = {};

    for (int k0 = 0; k0 < DMc; k0 += 16) {
        float4 av = *(const float4*)&X[(size_t)(m0 + lrow) * DMc + k0 + lkq * 4];
        *(float4*)&As[lrow][lkq * 4] = av;
        float4 wv = *(const float4*)&W[(size_t)(n0 + lrow) * DMc + k0 + lkq * 4];
        Bs[lkq * 4 + 0][lrow] = wv.x;
        Bs[lkq * 4 + 1][lrow] = wv.y;
        Bs[lkq * 4 + 2][lrow] = wv.z;
        Bs[lkq * 4 + 3][lrow] = wv.w;
        __syncthreads();

        #pragma unroll
        for (int kk = 0; kk < 16; kk++) {
            float a0 = As[ty * 4 + 0][kk];
            float a1 = As[ty * 4 + 1][kk];
            float a2 = As[ty * 4 + 2][kk];
            float a3 = As[ty * 4 + 3][kk];
            float4 b4 = *(float4*)&Bs[kk][tx * 4];
            acc[0][0] += a0 * b4.x; acc[0][1] += a0 * b4.y; acc[0][2] += a0 * b4.z; acc[0][3] += a0 * b4.w;
            acc[1][0] += a1 * b4.x; acc[1][1] += a1 * b4.y; acc[1][2] += a1 * b4.z; acc[1][3] += a1 * b4.w;
            acc[2][0] += a2 * b4.x; acc[2][1] += a2 * b4.y; acc[2][2] += a2 * b4.z; acc[2][3] += a2 * b4.w;
            acc[3][0] += a3 * b4.x; acc[3][1] += a3 * b4.y; acc[3][2] += a3 * b4.z; acc[3][3] += a3 * b4.w;
        }
        __syncthreads();
    }

    float bj[4];
    #pragma unroll
    for (int j = 0; j < 4; j++) bj[j] = bias[n0 + tx * 4 + j];

    const int h = n0 >> 6;  // tile N == head width == 64
    float* dst = (which == 0) ? g_q : (which == 1) ? g_k : g_v;

    #pragma unroll
    for (int i = 0; i < 4; i++) {
        int gr = m0 + ty * 4 + i;
        int bb = gr >> 12;          // / 4096
        int sg = gr & (Sc - 1);
        float vals[4];
        #pragma unroll
        for (int j = 0; j < 4; j++) vals[j] = acc[i][j] + bj[j];
        if (which < 2) {
            #pragma unroll
            for (int j = 0; j < 4; j++) {
                int d = tx * 4 + j;
                float part = __shfl_xor_sync(0xffffffffu, vals[j], 8);
                part = (tx < 8) ? -part : part;   // rotate_half partner: d<32 -> -x[d+32], else +x[d-32]
                float c = cosb[sg * HDc + d];
                float s = sinb[sg * HDc + d];
                vals[j] = vals[j] * c + part * s;
            }
        }
        *(float4*)&dst[(((size_t)(bb * Hc + h)) * Sc + sg) * HDc + tx * 4] =
            make_float4(vals[0], vals[1], vals[2], vals[3]);
    }
}

// ---------------------------------------------------------------------------
// fp32 flash attention. Grid: (S/64, B*H). 256 threads.
// Score scale = 1/HD (both HD^-0.5 factors of the reference folded in).
// ---------------------------------------------------------------------------
__global__ __launch_bounds__(256) void flash_kernel()
{
    extern __shared__ float sh[];
    float* Qs = sh;                     // [64][64]
    float* Kt = sh + 4096;              // [64][68] d-major (transposed K)
    float* Vs = sh + 4096 + 4352;       // [64][68]
    float* Ps = sh + 4096 + 2 * 4352;   // [64][68]

    const int tid = threadIdx.x;
    const int ty = tid >> 4, tx = tid & 15;
    const int bh = blockIdx.y;
    const int m0 = blockIdx.x * 64;

    const float* qb = g_q + (size_t)bh * Sc * HDc;
    const float* kb = g_k + (size_t)bh * Sc * HDc;
    const float* vb = g_v + (size_t)bh * Sc * HDc;

    // Load Q tile once
    #pragma unroll
    for (int p = 0; p < 4; p++) {
        int f = p * 256 + tid;
        int row = f >> 4, dq = f & 15;
        *(float4*)&Qs[row * 64 + dq * 4] =
            *(const float4*)&qb[(size_t)(m0 + row) * HDc + dq * 4];
    }

    float mrow[4], lrow[4], o[4][4];
    #pragma unroll
    for (int i = 0; i < 4; i++) {
        mrow[i] = -1e30f; lrow[i] = 0.f;
        #pragma unroll
        for (int j = 0; j < 4; j++) o[i][j] = 0.f;
    }

    const float scale = 1.0f / 64.0f;

    for (int n0 = 0; n0 < Sc; n0 += 64) {
        __syncthreads();   // protect Kt/Vs/Ps from previous iteration's readers
        #pragma unroll
        for (int p = 0; p < 4; p++) {
            int f = p * 256 + tid;
            int row = f >> 4, dq = f & 15;
            float4 kv = *(const float4*)&kb[(size_t)(n0 + row) * HDc + dq * 4];
            Kt[(dq * 4 + 0) * 68 + row] = kv.x;
            Kt[(dq * 4 + 1) * 68 + row] = kv.y;
            Kt[(dq * 4 + 2) * 68 + row] = kv.z;
            Kt[(dq * 4 + 3) * 68 + row] = kv.w;
            *(float4*)&Vs[row * 68 + dq * 4] =
                *(const float4*)&vb[(size_t)(n0 + row) * HDc + dq * 4];
        }
        __syncthreads();

        // S = Q K^T  (64x64x64)
        float sv[4][4] = {};
        #pragma unroll
        for (int d = 0; d < 64; d += 4) {
            float4 qv[4];
            #pragma unroll
            for (int i = 0; i < 4; i++)
                qv[i] = *(float4*)&Qs[(ty * 4 + i) * 64 + d];
            float4 k0 = *(float4*)&Kt[(d + 0) * 68 + tx * 4];
            float4 k1 = *(float4*)&Kt[(d + 1) * 68 + tx * 4];
            float4 k2 = *(float4*)&Kt[(d + 2) * 68 + tx * 4];
            float4 k3 = *(float4*)&Kt[(d + 3) * 68 + tx * 4];
            #pragma unroll
            for (int i = 0; i < 4; i++) {
                sv[i][0] += qv[i].x * k0.x + qv[i].y * k1.x + qv[i].z * k2.x + qv[i].w * k3.x;
                sv[i][1] += qv[i].x * k0.y + qv[i].y * k1.y + qv[i].z * k2.y + qv[i].w * k3.y;
                sv[i][2] += qv[i].x * k0.z + qv[i].y * k1.z + qv[i].z * k2.z + qv[i].w * k3.z;
                sv[i][3] += qv[i].x * k0.w + qv[i].y * k1.w + qv[i].z * k2.w + qv[i].w * k3.w;
            }
        }

        // Online softmax (row owned by 16 lanes: same ty, tx=0..15)
        #pragma unroll
        for (int i = 0; i < 4; i++) {
            #pragma unroll
            for (int j = 0; j < 4; j++) sv[i][j] *= scale;
            float tm = fmaxf(fmaxf(sv[i][0], sv[i][1]), fmaxf(sv[i][2], sv[i][3]));
            #pragma unroll
            for (int off = 8; off >= 1; off >>= 1)
                tm = fmaxf(tm, __shfl_xor_sync(0xffffffffu, tm, off));
            float mnew = fmaxf(mrow[i], tm);
            float alpha = __expf(mrow[i] - mnew);
            float rs = 0.f;
            #pragma unroll
            for (int j = 0; j < 4; j++) {
                float pp = __expf(sv[i][j] - mnew);
                sv[i][j] = pp;
                rs += pp;
            }
            #pragma unroll
            for (int off = 8; off >= 1; off >>= 1)
                rs += __shfl_xor_sync(0xffffffffu, rs, off);
            lrow[i] = lrow[i] * alpha + rs;
            mrow[i] = mnew;
            #pragma unroll
            for (int j = 0; j < 4; j++) o[i][j] *= alpha;
            *(float4*)&Ps[(ty * 4 + i) * 68 + tx * 4] =
                make_float4(sv[i][0], sv[i][1], sv[i][2], sv[i][3]);
        }
        __syncthreads();

        // O += P V  (64x64x64)
        #pragma unroll
        for (int n = 0; n < 64; n += 4) {
            float4 pr[4], vr[4];
            #pragma unroll
            for (int i = 0; i < 4; i++)
                pr[i] = *(float4*)&Ps[(ty * 4 + i) * 68 + n];
            #pragma unroll
            for (int t = 0; t < 4; t++)
                vr[t] = *(float4*)&Vs[(n + t) * 68 + tx * 4];
            #pragma unroll
            for (int i = 0; i < 4; i++) {
                float p0 = pr[i].x, p1 = pr[i].y, p2 = pr[i].z, p3 = pr[i].w;
                o[i][0] += p0 * vr[0].x + p1 * vr[1].x + p2 * vr[2].x + p3 * vr[3].x;
                o[i][1] += p0 * vr[0].y + p1 * vr[1].y + p2 * vr[2].y + p3 * vr[3].y;
                o[i][2] += p0 * vr[0].z + p1 * vr[1].z + p2 * vr[2].z + p3 * vr[3].z;
                o[i][3] += p0 * vr[0].w + p1 * vr[1].w + p2 * vr[2].w + p3 * vr[3].w;
            }
        }
    }

    // Normalize and write attn in [B,S,DM] layout (col = h*64 + d)
    const int b = bh / Hc, h = bh % Hc;
    #pragma unroll
    for (int i = 0; i < 4; i++) {
        float inv = 1.0f / lrow[i];
        int sg = m0 + ty * 4 + i;
        *(float4*)&g_attn[((size_t)(b * Sc + sg)) * DMc + h * HDc + tx * 4] =
            make_float4(o[i][0] * inv, o[i][1] * inv, o[i][2] * inv, o[i][3] * inv);
    }
}

// ---------------------------------------------------------------------------
// Output projection + residual: res = attn @ Wo^T + hidden
// ---------------------------------------------------------------------------
__global__ __launch_bounds__(256) void gemm_out(
    const float* __restrict__ hidden, const float* __restrict__ W)
{
    __shared__ float As[64][16];
    __shared__ float Bs[16][68];

    const int tid = threadIdx.x;
    const int ty = tid >> 4, tx = tid & 15;
    const int n0 = blockIdx.x * 64;
    const int m0 = blockIdx.y * 64;
    const int lrow = tid >> 2, lkq = tid & 3;

    float acc[4][4] = {};

    for (int k0 = 0; k0 < DMc; k0 += 16) {
        float4 av = *(const float4*)&g_attn[(size_t)(m0 + lrow) * DMc + k0 + lkq * 4];
        *(float4*)&As[lrow][lkq * 4] = av;
        float4 wv = *(const float4*)&W[(size_t)(n0 + lrow) * DMc + k0 + lkq * 4];
        Bs[lkq * 4 + 0][lrow] = wv.x;
        Bs[lkq * 4 + 1][lrow] = wv.y;
        Bs[lkq * 4 + 2][lrow] = wv.z;
        Bs[lkq * 4 + 3][lrow] = wv.w;
        __syncthreads();

        #pragma unroll
        for (int kk = 0; kk < 16; kk++) {
            float a0 = As[ty * 4 + 0][kk];
            float a1 = As[ty * 4 + 1][kk];
            float a2 = As[ty * 4 + 2][kk];
            float a3 = As[ty * 4 + 3][kk];
            float4 b4 = *(float4*)&Bs[kk][tx * 4];
            acc[0][0] += a0 * b4.x; acc[0][1] += a0 * b4.y; acc[0][2] += a0 * b4.z; acc[0][3] += a0 * b4.w;
            acc[1][0] += a1 * b4.x; acc[1][1] += a1 * b4.y; acc[1][2] += a1 * b4.z; acc[1][3] += a1 * b4.w;
            acc[2][0] += a2 * b4.x; acc[2][1] += a2 * b4.y; acc[2][2] += a2 * b4.z; acc[2][3] += a2 * b4.w;
            acc[3][0] += a3 * b4.x; acc[3][1] += a3 * b4.y; acc[3][2] += a3 * b4.z; acc[3][3] += a3 * b4.w;
        }
        __syncthreads();
    }

    #pragma unroll
    for (int i = 0; i < 4; i++) {
        int gr = m0 + ty * 4 + i;
        float4 r = *(const float4*)&hidden[(size_t)gr * DMc + n0 + tx * 4];
        *(float4*)&g_res[(size_t)gr * DMc + n0 + tx * 4] =
            make_float4(acc[i][0] + r.x, acc[i][1] + r.y, acc[i][2] + r.z, acc[i][3] + r.w);
    }
}

// ---------------------------------------------------------------------------
// LayerNorm: one block per row of 768
// ---------------------------------------------------------------------------
__global__ __launch_bounds__(256) void ln_kernel(
    const float* __restrict__ gam, const float* __restrict__ bet,
    float* __restrict__ out)
{
    const int row = blockIdx.x;
    const int tid = threadIdx.x;
    const float* x = g_res + (size_t)row * DMc;

    float v0 = x[tid], v1 = x[tid + 256], v2 = x[tid + 512];
    float s  = v0 + v1 + v2;
    float sq = v0 * v0 + v1 * v1 + v2 * v2;

    #pragma unroll
    for (int off = 16; off >= 1; off >>= 1) {
        s  += __shfl_xor_sync(0xffffffffu, s,  off);
        sq += __shfl_xor_sync(0xffffffffu, sq, off);
    }

    __shared__ float ws[8], wq[8];
    int w = tid >> 5, lane = tid & 31;
    if (lane == 0) { ws[w] = s; wq[w] = sq; }
    __syncthreads();
    s = 0.f; sq = 0.f;
    #pragma unroll
    for (int i = 0; i < 8; i++) { s += ws[i]; sq += wq[i]; }

    const float inv_n = 1.0f / 768.0f;
    float mu  = s * inv_n;
    float var = sq * inv_n - mu * mu;
    float inv = rsqrtf(var + 1e-12f);

    float* op = out + (size_t)row * DMc;
    op[tid]       = (v0 - mu) * inv * gam[tid]       + bet[tid];
    op[tid + 256] = (v1 - mu) * inv * gam[tid + 256] + bet[tid + 256];
    op[tid + 512] = (v2 - mu) * inv * gam[tid + 512] + bet[tid + 512];
}

// ---------------------------------------------------------------------------
extern "C" void kernel_launch(void* const* d_in, const int* in_sizes, int n_in,
                              void* d_out, int out_size)
{
    const float* hidden = (const float*)d_in[0];
    const float* cosb   = (const float*)d_in[1];
    const float* sinb   = (const float*)d_in[2];
    const float* Wq     = (const float*)d_in[3];
    const float* bq     = (const float*)d_in[4];
    const float* Wk     = (const float*)d_in[5];
    const float* bk     = (const float*)d_in[6];
    const float* Wv     = (const float*)d_in[7];
    const float* bv     = (const float*)d_in[8];
    const float* Wo     = (const float*)d_in[9];
    const float* lng    = (const float*)d_in[10];
    const float* lnb    = (const float*)d_in[11];
    float* out = (float*)d_out;

    dim3 gproj(DMc / 64, BSc / 64);   // (12, 128)

    gemm_proj<<<gproj, 256>>>(hidden, Wq, bq, cosb, sinb, 0);
    gemm_proj<<<gproj, 256>>>(hidden, Wk, bk, cosb, sinb, 1);
    gemm_proj<<<gproj, 256>>>(hidden, Wv, bv, cosb, sinb, 2);

    const int flash_smem = (64 * 64 + 3 * 64 * 68) * (int)sizeof(float);  // 68608
    cudaFuncSetAttribute(flash_kernel,
                         cudaFuncAttributeMaxDynamicSharedMemorySize, flash_smem);
    flash_kernel<<<dim3(Sc / 64, BHc), 256, flash_smem>>>();

    gemm_out<<<gproj, 256>>>(hidden, Wo);
    ln_kernel<<<BSc, 256>>>(lng, lnb, out);
}

// round 3
// speedup vs baseline: 3.2146x; 3.2146x over previous
#include <cuda_runtime.h>
#include <cstdint>

constexpr int Bc  = 2;
constexpr int Sc  = 4096;
constexpr int DMc = 768;
constexpr int Hc  = 12;
constexpr int HDc = 64;
constexpr int BSc = Bc * Sc;          // 8192 rows
constexpr int BHc = Bc * Hc;          // 24

// Device scratch (allocation-free contract)
__device__ float g_q[(size_t)BHc * Sc * HDc];
__device__ float g_k[(size_t)BHc * Sc * HDc];
__device__ float g_v[(size_t)BHc * Sc * HDc];
__device__ float g_attn[(size_t)BSc * DMc];
__device__ float g_res[(size_t)BSc * DMc];

// ---------------------------------------------------------------------------
// tf32 helpers
// ---------------------------------------------------------------------------
__device__ __forceinline__ uint32_t f2tf(float x) {
    uint32_t r;
    asm volatile("cvt.rna.tf32.f32 %0, %1;" : "=r"(r) : "f"(x));
    return r;
}
__device__ __forceinline__ float f2tff(float x) { return __uint_as_float(f2tf(x)); }

__device__ __forceinline__ void mma8(float c[4],
    uint32_t a0, uint32_t a1, uint32_t a2, uint32_t a3,
    uint32_t b0, uint32_t b1)
{
    asm volatile(
        "mma.sync.aligned.m16n8k8.row.col.f32.tf32.tf32.f32 "
        "{%0,%1,%2,%3},{%4,%5,%6,%7},{%8,%9},{%0,%1,%2,%3};"
        : "+f"(c[0]), "+f"(c[1]), "+f"(c[2]), "+f"(c[3])
        : "r"(a0), "r"(a1), "r"(a2), "r"(a3), "r"(b0), "r"(b1));
}

// ---------------------------------------------------------------------------
// Tensor-core GEMM: C[m][n] = sum_k A[m][k] * W[n][k] (+bias) (+RoPE / +resid)
// Tile 128x64, Kc=32, 256 threads = 8 warps, warp = 16 rows x 64 cols.
// mode: 0=q(rope) 1=k(rope) 2=v(bias only) 3=out(residual add -> g_res)
// ---------------------------------------------------------------------------
__global__ __launch_bounds__(256) void gemm_mma(
    const float* __restrict__ A, const float* __restrict__ W,
    const float* __restrict__ bias,
    const float* __restrict__ cosb, const float* __restrict__ sinb,
    const float* __restrict__ resid, int mode)
{
    __shared__ float Xs[128][36];   // stride 36: frag bank = 4*(lane/4)+lane%4, conflict-free
    __shared__ float Ws[64][36];

    const int tid  = threadIdx.x;
    const int lane = tid & 31, wrp = tid >> 5;
    const int g = lane >> 2, q = lane & 3;
    const int m0 = blockIdx.y * 128, n0 = blockIdx.x * 64;

    const float* Ap = (mode == 3) ? g_attn : A;

    float c[8][4] = {};

    for (int k0 = 0; k0 < DMc; k0 += 32) {
        __syncthreads();
        #pragma unroll
        for (int p = 0; p < 4; p++) {
            int f = p * 256 + tid;
            int row = f >> 3, c4 = (f & 7) * 4;
            float4 v = *(const float4*)&Ap[(size_t)(m0 + row) * DMc + k0 + c4];
            *(float4*)&Xs[row][c4] =
                make_float4(f2tff(v.x), f2tff(v.y), f2tff(v.z), f2tff(v.w));
        }
        #pragma unroll
        for (int p = 0; p < 2; p++) {
            int f = p * 256 + tid;
            int row = f >> 3, c4 = (f & 7) * 4;
            float4 v = *(const float4*)&W[(size_t)(n0 + row) * DMc + k0 + c4];
            *(float4*)&Ws[row][c4] =
                make_float4(f2tff(v.x), f2tff(v.y), f2tff(v.z), f2tff(v.w));
        }
        __syncthreads();

        #pragma unroll
        for (int ks = 0; ks < 4; ks++) {
            int kk = ks * 8;
            uint32_t a0 = __float_as_uint(Xs[wrp * 16 + g    ][kk + q    ]);
            uint32_t a1 = __float_as_uint(Xs[wrp * 16 + g + 8][kk + q    ]);
            uint32_t a2 = __float_as_uint(Xs[wrp * 16 + g    ][kk + q + 4]);
            uint32_t a3 = __float_as_uint(Xs[wrp * 16 + g + 8][kk + q + 4]);
            #pragma unroll
            for (int nt = 0; nt < 8; nt++) {
                uint32_t b0 = __float_as_uint(Ws[nt * 8 + g][kk + q    ]);
                uint32_t b1 = __float_as_uint(Ws[nt * 8 + g][kk + q + 4]);
                mma8(c[nt], a0, a1, a2, a3, b0, b1);
            }
        }
    }

    // ---- epilogue ----
    if (mode <= 1) {
        float* dst = (mode == 0) ? g_q : g_k;
        const int h = blockIdx.x;     // N-tile == head
        #pragma unroll
        for (int rr = 0; rr < 2; rr++) {
            int row = m0 + wrp * 16 + g + rr * 8;
            int bb = row >> 12, sg = row & (Sc - 1);
            size_t base = (((size_t)(bb * Hc + h)) * Sc + sg) * HDc;
            #pragma unroll
            for (int nt = 0; nt < 4; nt++) {
                int d = nt * 8 + q * 2;      // d in [0,32)
                float lo0 = c[nt][rr * 2 + 0]     + bias[n0 + d];
                float lo1 = c[nt][rr * 2 + 1]     + bias[n0 + d + 1];
                float hi0 = c[nt + 4][rr * 2 + 0] + bias[n0 + d + 32];
                float hi1 = c[nt + 4][rr * 2 + 1] + bias[n0 + d + 33];
                float c0 = cosb[sg * HDc + d],     c1 = cosb[sg * HDc + d + 1];
                float s0 = sinb[sg * HDc + d],     s1 = sinb[sg * HDc + d + 1];
                // cos/sin[d+32] == cos/sin[d] (concat(freqs,freqs))
                *(float2*)&dst[base + d] =
                    make_float2(lo0 * c0 - hi0 * s0, lo1 * c1 - hi1 * s1);
                *(float2*)&dst[base + d + 32] =
                    make_float2(hi0 * c0 + lo0 * s0, hi1 * c1 + lo1 * s1);
            }
        }
    } else if (mode == 2) {
        const int h = blockIdx.x;
        #pragma unroll
        for (int rr = 0; rr < 2; rr++) {
            int row = m0 + wrp * 16 + g + rr * 8;
            int bb = row >> 12, sg = row & (Sc - 1);
            size_t base = (((size_t)(bb * Hc + h)) * Sc + sg) * HDc;
            #pragma unroll
            for (int nt = 0; nt < 8; nt++) {
                int d = nt * 8 + q * 2;
                *(float2*)&g_v[base + d] =
                    make_float2(c[nt][rr * 2 + 0] + bias[n0 + d],
                                c[nt][rr * 2 + 1] + bias[n0 + d + 1]);
            }
        }
    } else {
        #pragma unroll
        for (int rr = 0; rr < 2; rr++) {
            int row = m0 + wrp * 16 + g + rr * 8;
            #pragma unroll
            for (int nt = 0; nt < 8; nt++) {
                int col = n0 + nt * 8 + q * 2;
                float2 r = *(const float2*)&resid[(size_t)row * DMc + col];
                *(float2*)&g_res[(size_t)row * DMc + col] =
                    make_float2(c[nt][rr * 2 + 0] + r.x, c[nt][rr * 2 + 1] + r.y);
            }
        }
    }
}

// ---------------------------------------------------------------------------
// tf32 flash attention. BM=128, BN=64, HD=64. Grid (S/128, B*H), 256 threads.
// Warp owns 16 q-rows x full 64 keys -> warp-local online softmax.
// ---------------------------------------------------------------------------
__global__ __launch_bounds__(256, 2) void flash_mma()
{
    extern __shared__ float sh[];
    float* Qs = sh;                    // [128][68]
    float* Ks = Qs + 128 * 68;         // [64][68]
    float* Ps = Ks + 64 * 68;          // [128][68]
    float* Vs = Ps + 128 * 68;         // [64][72]

    const int tid  = threadIdx.x;
    const int lane = tid & 31, wrp = tid >> 5;
    const int g = lane >> 2, q = lane & 3;
    const int bh = blockIdx.y, m0 = blockIdx.x * 128;

    const float* qb = g_q + (size_t)bh * Sc * HDc;
    const float* kb = g_k + (size_t)bh * Sc * HDc;
    const float* vb = g_v + (size_t)bh * Sc * HDc;

    // Q tile (scale 1/64 folded in; exact power of two)
    #pragma unroll
    for (int p = 0; p < 8; p++) {
        int f = p * 256 + tid;
        int row = f >> 4, c4 = (f & 15) * 4;
        float4 v = *(const float4*)&qb[(size_t)(m0 + row) * HDc + c4];
        const float sc = 1.0f / 64.0f;
        *(float4*)&Qs[row * 68 + c4] = make_float4(
            f2tff(v.x * sc), f2tff(v.y * sc), f2tff(v.z * sc), f2tff(v.w * sc));
    }

    float o[8][4] = {};
    float mstat[2] = { -1e30f, -1e30f };
    float lstat[2] = { 0.f, 0.f };

    for (int n0t = 0; n0t < Sc; n0t += 64) {
        __syncthreads();
        #pragma unroll
        for (int p = 0; p < 4; p++) {
            int f = p * 256 + tid;
            int row = f >> 4, c4 = (f & 15) * 4;
            float4 kv = *(const float4*)&kb[(size_t)(n0t + row) * HDc + c4];
            *(float4*)&Ks[row * 68 + c4] =
                make_float4(f2tff(kv.x), f2tff(kv.y), f2tff(kv.z), f2tff(kv.w));
            float4 vv = *(const float4*)&vb[(size_t)(n0t + row) * HDc + c4];
            *(float4*)&Vs[row * 72 + c4] =
                make_float4(f2tff(vv.x), f2tff(vv.y), f2tff(vv.z), f2tff(vv.w));
        }
        __syncthreads();

        // S = Q K^T
        float s[8][4] = {};
        #pragma unroll
        for (int ks = 0; ks < 8; ks++) {
            int kk = ks * 8;
            uint32_t a0 = __float_as_uint(Qs[(wrp * 16 + g    ) * 68 + kk + q    ]);
            uint32_t a1 = __float_as_uint(Qs[(wrp * 16 + g + 8) * 68 + kk + q    ]);
            uint32_t a2 = __float_as_uint(Qs[(wrp * 16 + g    ) * 68 + kk + q + 4]);
            uint32_t a3 = __float_as_uint(Qs[(wrp * 16 + g + 8) * 68 + kk + q + 4]);
            #pragma unroll
            for (int nt = 0; nt < 8; nt++) {
                uint32_t b0 = __float_as_uint(Ks[(nt * 8 + g) * 68 + kk + q    ]);
                uint32_t b1 = __float_as_uint(Ks[(nt * 8 + g) * 68 + kk + q + 4]);
                mma8(s[nt], a0, a1, a2, a3, b0, b1);
            }
        }

        // warp-local online softmax (rows wrp*16+g and +8)
        #pragma unroll
        for (int rr = 0; rr < 2; rr++) {
            float mx = -1e30f;
            #pragma unroll
            for (int nt = 0; nt < 8; nt++)
                mx = fmaxf(mx, fmaxf(s[nt][rr * 2], s[nt][rr * 2 + 1]));
            mx = fmaxf(mx, __shfl_xor_sync(0xffffffffu, mx, 1));
            mx = fmaxf(mx, __shfl_xor_sync(0xffffffffu, mx, 2));
            float mnew  = fmaxf(mstat[rr], mx);
            float alpha = __expf(mstat[rr] - mnew);
            mstat[rr] = mnew;
            float sum = 0.f;
            #pragma unroll
            for (int nt = 0; nt < 8; nt++) {
                float e0 = __expf(s[nt][rr * 2]     - mnew);
                float e1 = __expf(s[nt][rr * 2 + 1] - mnew);
                s[nt][rr * 2] = e0; s[nt][rr * 2 + 1] = e1;
                sum += e0 + e1;
            }
            sum += __shfl_xor_sync(0xffffffffu, sum, 1);
            sum += __shfl_xor_sync(0xffffffffu, sum, 2);
            lstat[rr] = lstat[rr] * alpha + sum;
            #pragma unroll
            for (int nt = 0; nt < 8; nt++) {
                o[nt][rr * 2] *= alpha; o[nt][rr * 2 + 1] *= alpha;
            }
        }

        // P -> smem (tf32-rounded)
        #pragma unroll
        for (int rr = 0; rr < 2; rr++) {
            int row = wrp * 16 + g + rr * 8;
            #pragma unroll
            for (int nt = 0; nt < 8; nt++) {
                *(float2*)&Ps[row * 68 + nt * 8 + q * 2] =
                    make_float2(f2tff(s[nt][rr * 2]), f2tff(s[nt][rr * 2 + 1]));
            }
        }
        __syncthreads();

        // O += P V
        #pragma unroll
        for (int ks = 0; ks < 8; ks++) {
            int kk = ks * 8;
            uint32_t a0 = __float_as_uint(Ps[(wrp * 16 + g    ) * 68 + kk + q    ]);
            uint32_t a1 = __float_as_uint(Ps[(wrp * 16 + g + 8) * 68 + kk + q    ]);
            uint32_t a2 = __float_as_uint(Ps[(wrp * 16 + g    ) * 68 + kk + q + 4]);
            uint32_t a3 = __float_as_uint(Ps[(wrp * 16 + g + 8) * 68 + kk + q + 4]);
            #pragma unroll
            for (int nt = 0; nt < 8; nt++) {
                uint32_t b0 = __float_as_uint(Vs[(kk + q    ) * 72 + nt * 8 + g]);
                uint32_t b1 = __float_as_uint(Vs[(kk + q + 4) * 72 + nt * 8 + g]);
                mma8(o[nt], a0, a1, a2, a3, b0, b1);
            }
        }
    }

    // epilogue: normalize, write [B,S,DM]
    const int b = bh / Hc, h = bh % Hc;
    #pragma unroll
    for (int rr = 0; rr < 2; rr++) {
        int row = m0 + wrp * 16 + g + rr * 8;
        float inv = 1.0f / lstat[rr];
        size_t base = ((size_t)(b * Sc + row)) * DMc + h * HDc;
        #pragma unroll
        for (int nt = 0; nt < 8; nt++) {
            *(float2*)&g_attn[base + nt * 8 + q * 2] =
                make_float2(o[nt][rr * 2] * inv, o[nt][rr * 2 + 1] * inv);
        }
    }
}

// ---------------------------------------------------------------------------
// LayerNorm: one block per row of 768
// ---------------------------------------------------------------------------
__global__ __launch_bounds__(256) void ln_kernel(
    const float* __restrict__ gam, const float* __restrict__ bet,
    float* __restrict__ out)
{
    const int row = blockIdx.x;
    const int tid = threadIdx.x;
    const float* x = g_res + (size_t)row * DMc;

    float v0 = x[tid], v1 = x[tid + 256], v2 = x[tid + 512];
    float s  = v0 + v1 + v2;
    float sq = v0 * v0 + v1 * v1 + v2 * v2;

    #pragma unroll
    for (int off = 16; off >= 1; off >>= 1) {
        s  += __shfl_xor_sync(0xffffffffu, s,  off);
        sq += __shfl_xor_sync(0xffffffffu, sq, off);
    }

    __shared__ float ws[8], wq[8];
    int w = tid >> 5, lane = tid & 31;
    if (lane == 0) { ws[w] = s; wq[w] = sq; }
    __syncthreads();
    s = 0.f; sq = 0.f;
    #pragma unroll
    for (int i = 0; i < 8; i++) { s += ws[i]; sq += wq[i]; }

    const float inv_n = 1.0f / 768.0f;
    float mu  = s * inv_n;
    float var = sq * inv_n - mu * mu;
    float inv = rsqrtf(var + 1e-12f);

    float* op = out + (size_t)row * DMc;
    op[tid]       = (v0 - mu) * inv * gam[tid]       + bet[tid];
    op[tid + 256] = (v1 - mu) * inv * gam[tid + 256] + bet[tid + 256];
    op[tid + 512] = (v2 - mu) * inv * gam[tid + 512] + bet[tid + 512];
}

// ---------------------------------------------------------------------------
extern "C" void kernel_launch(void* const* d_in, const int* in_sizes, int n_in,
                              void* d_out, int out_size)
{
    const float* hidden = (const float*)d_in[0];
    const float* cosb   = (const float*)d_in[1];
    const float* sinb   = (const float*)d_in[2];
    const float* Wq     = (const float*)d_in[3];
    const float* bq     = (const float*)d_in[4];
    const float* Wk     = (const float*)d_in[5];
    const float* bk     = (const float*)d_in[6];
    const float* Wv     = (const float*)d_in[7];
    const float* bv     = (const float*)d_in[8];
    const float* Wo     = (const float*)d_in[9];
    const float* lng    = (const float*)d_in[10];
    const float* lnb    = (const float*)d_in[11];
    float* out = (float*)d_out;

    dim3 gg(DMc / 64, BSc / 128);   // (12, 64)

    gemm_mma<<<gg, 256>>>(hidden, Wq, bq, cosb, sinb, nullptr, 0);
    gemm_mma<<<gg, 256>>>(hidden, Wk, bk, cosb, sinb, nullptr, 1);
    gemm_mma<<<gg, 256>>>(hidden, Wv, bv, cosb, sinb, nullptr, 2);

    const int flash_smem = (128 * 68 + 64 * 68 + 128 * 68 + 64 * 72) * (int)sizeof(float);
    cudaFuncSetAttribute(flash_mma,
                         cudaFuncAttributeMaxDynamicSharedMemorySize, flash_smem);
    flash_mma<<<dim3(Sc / 128, BHc), 256, flash_smem>>>();

    gemm_mma<<<gg, 256>>>(hidden, Wo, nullptr, cosb, sinb, hidden, 3);
    ln_kernel<<<BSc, 256>>>(lng, lnb, out);
}

// round 5
// speedup vs baseline: 3.2207x; 1.0019x over previous
#include <cuda_runtime.h>
#include <cstdint>

constexpr int Bc  = 2;
constexpr int Sc  = 4096;
constexpr int DMc = 768;
constexpr int Hc  = 12;
constexpr int HDc = 64;
constexpr int BSc = Bc * Sc;          // 8192 rows
constexpr int BHc = Bc * Hc;          // 24

// Device scratch (allocation-free contract)
__device__ float g_q[(size_t)BHc * Sc * HDc];     // tf32-rounded, pre-scaled by 1/64
__device__ float g_k[(size_t)BHc * Sc * HDc];     // tf32-rounded
__device__ float g_v[(size_t)BHc * Sc * HDc];     // tf32-rounded
__device__ float g_attn[(size_t)BSc * DMc];
__device__ float g_res[(size_t)BSc * DMc];

// ---------------------------------------------------------------------------
// helpers
// ---------------------------------------------------------------------------
__device__ __forceinline__ uint32_t f2tf(float x) {
    uint32_t r;
    asm volatile("cvt.rna.tf32.f32 %0, %1;" : "=r"(r) : "f"(x));
    return r;
}
__device__ __forceinline__ float f2tff(float x) { return __uint_as_float(f2tf(x)); }

__device__ __forceinline__ void mma8(float c[4],
    uint32_t a0, uint32_t a1, uint32_t a2, uint32_t a3,
    uint32_t b0, uint32_t b1)
{
    asm volatile(
        "mma.sync.aligned.m16n8k8.row.col.f32.tf32.tf32.f32 "
        "{%0,%1,%2,%3},{%4,%5,%6,%7},{%8,%9},{%0,%1,%2,%3};"
        : "+f"(c[0]), "+f"(c[1]), "+f"(c[2]), "+f"(c[3])
        : "r"(a0), "r"(a1), "r"(a2), "r"(a3), "r"(b0), "r"(b1));
}

__device__ __forceinline__ void cp16(float* dst_smem, const float* src) {
    uint32_t d = (uint32_t)__cvta_generic_to_shared(dst_smem);
    asm volatile("cp.async.ca.shared.global [%0], [%1], 16;\n" :: "r"(d), "l"(src));
}
__device__ __forceinline__ void cp_commit() {
    asm volatile("cp.async.commit_group;\n");
}
template<int N> __device__ __forceinline__ void cp_wait() {
    asm volatile("cp.async.wait_group %0;\n" :: "n"(N));
}

// ---------------------------------------------------------------------------
// Tensor-core GEMM: C[m][n] = sum_k A[m][k] * W[n][k] (+bias) (+RoPE / +resid)
// Tile 128x64, Kc=32, 256 threads = 8 warps, warp = 16 rows x 64 cols.
// Register-staged prefetch of the next K-chunk.
// mode: 0=q(rope, *1/64, tf32 store) 1=k(rope, tf32) 2=v(bias, tf32)
//       3=out(residual add -> g_res, fp32)
// ---------------------------------------------------------------------------
__global__ __launch_bounds__(256) void gemm_mma(
    const float* __restrict__ A, const float* __restrict__ W,
    const float* __restrict__ bias,
    const float* __restrict__ cosb, const float* __restrict__ sinb,
    const float* __restrict__ resid, int mode)
{
    __shared__ float Xs[128][36];   // stride 36: conflict-free fragment loads
    __shared__ float Ws[64][36];

    const int tid  = threadIdx.x;
    const int lane = tid & 31, wrp = tid >> 5;
    const int g = lane >> 2, q = lane & 3;
    const int m0 = blockIdx.y * 128, n0 = blockIdx.x * 64;

    const float* Ap = (mode == 3) ? g_attn : A;

    const int tr  = tid >> 3;          // 0..31
    const int lc4 = (tid & 7) * 4;     // 0..28

    float4 xr[4], wr[2];
    #pragma unroll
    for (int p = 0; p < 4; p++)
        xr[p] = *(const float4*)&Ap[(size_t)(m0 + p * 32 + tr) * DMc + lc4];
    #pragma unroll
    for (int p = 0; p < 2; p++)
        wr[p] = *(const float4*)&W[(size_t)(n0 + p * 32 + tr) * DMc + lc4];

    float c[8][4] = {};

    for (int k0 = 0; k0 < DMc; k0 += 32) {
        #pragma unroll
        for (int p = 0; p < 4; p++)
            *(float4*)&Xs[p * 32 + tr][lc4] = make_float4(
                f2tff(xr[p].x), f2tff(xr[p].y), f2tff(xr[p].z), f2tff(xr[p].w));
        #pragma unroll
        for (int p = 0; p < 2; p++)
            *(float4*)&Ws[p * 32 + tr][lc4] = make_float4(
                f2tff(wr[p].x), f2tff(wr[p].y), f2tff(wr[p].z), f2tff(wr[p].w));
        __syncthreads();

        if (k0 + 32 < DMc) {
            #pragma unroll
            for (int p = 0; p < 4; p++)
                xr[p] = *(const float4*)&Ap[(size_t)(m0 + p * 32 + tr) * DMc + k0 + 32 + lc4];
            #pragma unroll
            for (int p = 0; p < 2; p++)
                wr[p] = *(const float4*)&W[(size_t)(n0 + p * 32 + tr) * DMc + k0 + 32 + lc4];
        }

        #pragma unroll
        for (int ks = 0; ks < 4; ks++) {
            int kk = ks * 8;
            uint32_t a0 = __float_as_uint(Xs[wrp * 16 + g    ][kk + q    ]);
            uint32_t a1 = __float_as_uint(Xs[wrp * 16 + g + 8][kk + q    ]);
            uint32_t a2 = __float_as_uint(Xs[wrp * 16 + g    ][kk + q + 4]);
            uint32_t a3 = __float_as_uint(Xs[wrp * 16 + g + 8][kk + q + 4]);
            #pragma unroll
            for (int nt = 0; nt < 8; nt++) {
                uint32_t b0 = __float_as_uint(Ws[nt * 8 + g][kk + q    ]);
                uint32_t b1 = __float_as_uint(Ws[nt * 8 + g][kk + q + 4]);
                mma8(c[nt], a0, a1, a2, a3, b0, b1);
            }
        }
        __syncthreads();
    }

    // ---- epilogue ----
    if (mode <= 1) {
        float* dst = (mode == 0) ? g_q : g_k;
        const float post = (mode == 0) ? (1.0f / 64.0f) : 1.0f;
        const int h = blockIdx.x;     // N-tile == head
        #pragma unroll
        for (int rr = 0; rr < 2; rr++) {
            int row = m0 + wrp * 16 + g + rr * 8;
            int bb = row >> 12, sg = row & (Sc - 1);
            size_t base = (((size_t)(bb * Hc + h)) * Sc + sg) * HDc;
            #pragma unroll
            for (int nt = 0; nt < 4; nt++) {
                int d = nt * 8 + q * 2;      // d in [0,32)
                float lo0 = c[nt][rr * 2 + 0]     + bias[n0 + d];
                float lo1 = c[nt][rr * 2 + 1]     + bias[n0 + d + 1];
                float hi0 = c[nt + 4][rr * 2 + 0] + bias[n0 + d + 32];
                float hi1 = c[nt + 4][rr * 2 + 1] + bias[n0 + d + 33];
                float c0 = cosb[sg * HDc + d],     c1 = cosb[sg * HDc + d + 1];
                float s0 = sinb[sg * HDc + d],     s1 = sinb[sg * HDc + d + 1];
                // cos/sin[d+32] == cos/sin[d] (concat(freqs,freqs))
                *(float2*)&dst[base + d] = make_float2(
                    f2tff((lo0 * c0 - hi0 * s0) * post),
                    f2tff((lo1 * c1 - hi1 * s1) * post));
                *(float2*)&dst[base + d + 32] = make_float2(
                    f2tff((hi0 * c0 + lo0 * s0) * post),
                    f2tff((hi1 * c1 + lo1 * s1) * post));
            }
        }
    } else if (mode == 2) {
        const int h = blockIdx.x;
        #pragma unroll
        for (int rr = 0; rr < 2; rr++) {
            int row = m0 + wrp * 16 + g + rr * 8;
            int bb = row >> 12, sg = row & (Sc - 1);
            size_t base = (((size_t)(bb * Hc + h)) * Sc + sg) * HDc;
            #pragma unroll
            for (int nt = 0; nt < 8; nt++) {
                int d = nt * 8 + q * 2;
                *(float2*)&g_v[base + d] = make_float2(
                    f2tff(c[nt][rr * 2 + 0] + bias[n0 + d]),
                    f2tff(c[nt][rr * 2 + 1] + bias[n0 + d + 1]));
            }
        }
    } else {
        #pragma unroll
        for (int rr = 0; rr < 2; rr++) {
            int row = m0 + wrp * 16 + g + rr * 8;
            #pragma unroll
            for (int nt = 0; nt < 8; nt++) {
                int col = n0 + nt * 8 + q * 2;
                float2 r = *(const float2*)&resid[(size_t)row * DMc + col];
                *(float2*)&g_res[(size_t)row * DMc + col] =
                    make_float2(c[nt][rr * 2 + 0] + r.x, c[nt][rr * 2 + 1] + r.y);
            }
        }
    }
}

// ---------------------------------------------------------------------------
// tf32 flash attention. BM=128, BN=64, HD=64. Grid (S/128, B*H), 256 threads.
// q/k/v pre-rounded tf32 (q pre-scaled 1/64).
// cp.async double-buffered K/V; P kept in registers via intra-quad shuffles.
// ---------------------------------------------------------------------------
__device__ __forceinline__ void ldkv(
    const float* kb, const float* vb, int n0t,
    float* Kd, float* Vd, int tid)
{
    #pragma unroll
    for (int p = 0; p < 4; p++) {
        int f = p * 256 + tid;
        int row = f >> 4, c4 = (f & 15) * 4;
        cp16(&Kd[row * 68 + c4], &kb[(size_t)(n0t + row) * HDc + c4]);
        cp16(&Vd[row * 72 + c4], &vb[(size_t)(n0t + row) * HDc + c4]);
    }
}

__global__ __launch_bounds__(256, 2) void flash_mma()
{
    extern __shared__ float sh[];
    float* Qs = sh;                    // [128][68]
    float* K0 = sh + 128 * 68;         // [64][68]
    float* K1 = K0 + 64 * 68;
    float* V0 = K1 + 64 * 68;          // [64][72]
    float* V1 = V0 + 64 * 72;

    const int tid  = threadIdx.x;
    const int lane = tid & 31, wrp = tid >> 5;
    const int g = lane >> 2, q = lane & 3;
    const int bh = blockIdx.y, m0 = blockIdx.x * 128;

    const float* qb = g_q + (size_t)bh * Sc * HDc;
    const float* kb = g_k + (size_t)bh * Sc * HDc;
    const float* vb = g_v + (size_t)bh * Sc * HDc;

    // async Q + first two K/V tiles
    #pragma unroll
    for (int p = 0; p < 8; p++) {
        int f = p * 256 + tid;
        int row = f >> 4, c4 = (f & 15) * 4;
        cp16(&Qs[row * 68 + c4], &qb[(size_t)(m0 + row) * HDc + c4]);
    }
    ldkv(kb, vb, 0, K0, V0, tid);
    cp_commit();                       // group: Q + tile0
    ldkv(kb, vb, 64, K1, V1, tid);
    cp_commit();                       // group: tile1
    cp_wait<1>();
    __syncthreads();

    float o[8][4] = {};
    float mst[2] = { -1e30f, -1e30f };
    float lst[2] = { 0.f, 0.f };

    const int rowA  = (wrp * 16 + g) * 68;
    const int rowA8 = rowA + 8 * 68;
    const int srcA = q >> 1, srcB = srcA + 2;
    const bool odd = (q & 1);

    #pragma unroll 1
    for (int t = 0; t < Sc / 64; t++) {
        float* Ks = (t & 1) ? K1 : K0;
        float* Vs = (t & 1) ? V1 : V0;

        // S = Q K^T
        float s[8][4] = {};
        #pragma unroll
        for (int ks = 0; ks < 8; ks++) {
            int kk = ks * 8;
            uint32_t a0 = __float_as_uint(Qs[rowA  + kk + q    ]);
            uint32_t a1 = __float_as_uint(Qs[rowA8 + kk + q    ]);
            uint32_t a2 = __float_as_uint(Qs[rowA  + kk + q + 4]);
            uint32_t a3 = __float_as_uint(Qs[rowA8 + kk + q + 4]);
            #pragma unroll
            for (int nt = 0; nt < 8; nt++) {
                uint32_t b0 = __float_as_uint(Ks[(nt * 8 + g) * 68 + kk + q    ]);
                uint32_t b1 = __float_as_uint(Ks[(nt * 8 + g) * 68 + kk + q + 4]);
                mma8(s[nt], a0, a1, a2, a3, b0, b1);
            }
        }

        // warp-local online softmax (rows wrp*16+g and +8)
        #pragma unroll
        for (int rr = 0; rr < 2; rr++) {
            float mx = -1e30f;
            #pragma unroll
            for (int nt = 0; nt < 8; nt++)
                mx = fmaxf(mx, fmaxf(s[nt][rr * 2], s[nt][rr * 2 + 1]));
            mx = fmaxf(mx, __shfl_xor_sync(0xffffffffu, mx, 1));
            mx = fmaxf(mx, __shfl_xor_sync(0xffffffffu, mx, 2));
            float mnew  = fmaxf(mst[rr], mx);
            float alpha = __expf(mst[rr] - mnew);
            mst[rr] = mnew;
            float sum = 0.f;
            #pragma unroll
            for (int nt = 0; nt < 8; nt++) {
                float e0 = __expf(s[nt][rr * 2]     - mnew);
                float e1 = __expf(s[nt][rr * 2 + 1] - mnew);
                sum += e0 + e1;
                s[nt][rr * 2]     = f2tff(e0);
                s[nt][rr * 2 + 1] = f2tff(e1);
            }
            sum += __shfl_xor_sync(0xffffffffu, sum, 1);
            sum += __shfl_xor_sync(0xffffffffu, sum, 2);
            lst[rr] = lst[rr] * alpha + sum;
            #pragma unroll
            for (int nt = 0; nt < 8; nt++) {
                o[nt][rr * 2] *= alpha; o[nt][rr * 2 + 1] *= alpha;
            }
        }

        // O += P V   (P fragments built from s via intra-quad shuffles)
        #pragma unroll
        for (int ks = 0; ks < 8; ks++) {
            int kk = ks * 8;
            float t0 = __shfl_sync(0xffffffffu, s[ks][0], srcA, 4);
            float t1 = __shfl_sync(0xffffffffu, s[ks][1], srcA, 4);
            float t2 = __shfl_sync(0xffffffffu, s[ks][2], srcA, 4);
            float t3 = __shfl_sync(0xffffffffu, s[ks][3], srcA, 4);
            float u0 = __shfl_sync(0xffffffffu, s[ks][0], srcB, 4);
            float u1 = __shfl_sync(0xffffffffu, s[ks][1], srcB, 4);
            float u2 = __shfl_sync(0xffffffffu, s[ks][2], srcB, 4);
            float u3 = __shfl_sync(0xffffffffu, s[ks][3], srcB, 4);
            uint32_t a0 = __float_as_uint(odd ? t1 : t0);   // row g,   col kk+q
            uint32_t a1 = __float_as_uint(odd ? t3 : t2);   // row g+8, col kk+q
            uint32_t a2 = __float_as_uint(odd ? u1 : u0);   // row g,   col kk+q+4
            uint32_t a3 = __float_as_uint(odd ? u3 : u2);   // row g+8, col kk+q+4
            #pragma unroll
            for (int nt = 0; nt < 8; nt++) {
                uint32_t b0 = __float_as_uint(Vs[(kk + q    ) * 72 + nt * 8 + g]);
                uint32_t b1 = __float_as_uint(Vs[(kk + q + 4) * 72 + nt * 8 + g]);
                mma8(o[nt], a0, a1, a2, a3, b0, b1);
            }
        }

        if (t == Sc / 64 - 1) break;
        __syncthreads();                      // everyone done reading buf t&1
        if (t + 2 < Sc / 64) {
            ldkv(kb, vb, (t + 2) * 64, (t & 1) ? K1 : K0, (t & 1) ? V1 : V0, tid);
            cp_commit();
            cp_wait<1>();                     // tile t+1 group complete
        } else {
            cp_wait<0>();
        }
        __syncthreads();
    }

    // epilogue: normalize, write [B,S,DM]
    const int b = bh / Hc, h = bh % Hc;
    #pragma unroll
    for (int rr = 0; rr < 2; rr++) {
        int row = m0 + wrp * 16 + g + rr * 8;
        float inv = 1.0f / lst[rr];
        size_t base = ((size_t)(b * Sc + row)) * DMc + h * HDc;
        #pragma unroll
        for (int nt = 0; nt < 8; nt++) {
            *(float2*)&g_attn[base + nt * 8 + q * 2] =
                make_float2(o[nt][rr * 2] * inv, o[nt][rr * 2 + 1] * inv);
        }
    }
}

// ---------------------------------------------------------------------------
// LayerNorm: one block per row of 768
// ---------------------------------------------------------------------------
__global__ __launch_bounds__(256) void ln_kernel(
    const float* __restrict__ gam, const float* __restrict__ bet,
    float* __restrict__ out)
{
    const int row = blockIdx.x;
    const int tid = threadIdx.x;
    const float* x = g_res + (size_t)row * DMc;

    float v0 = x[tid], v1 = x[tid + 256], v2 = x[tid + 512];
    float s  = v0 + v1 + v2;
    float sq = v0 * v0 + v1 * v1 + v2 * v2;

    #pragma unroll
    for (int off = 16; off >= 1; off >>= 1) {
        s  += __shfl_xor_sync(0xffffffffu, s,  off);
        sq += __shfl_xor_sync(0xffffffffu, sq, off);
    }

    __shared__ float ws[8], wq[8];
    int w = tid >> 5, lane = tid & 31;
    if (lane == 0) { ws[w] = s; wq[w] = sq; }
    __syncthreads();
    s = 0.f; sq = 0.f;
    #pragma unroll
    for (int i = 0; i < 8; i++) { s += ws[i]; sq += wq[i]; }

    const float inv_n = 1.0f / 768.0f;
    float mu  = s * inv_n;
    float var = sq * inv_n - mu * mu;
    float inv = rsqrtf(var + 1e-12f);

    float* op = out + (size_t)row * DMc;
    op[tid]       = (v0 - mu) * inv * gam[tid]       + bet[tid];
    op[tid + 256] = (v1 - mu) * inv * gam[tid + 256] + bet[tid + 256];
    op[tid + 512] = (v2 - mu) * inv * gam[tid + 512] + bet[tid + 512];
}

// ---------------------------------------------------------------------------
extern "C" void kernel_launch(void* const* d_in, const int* in_sizes, int n_in,
                              void* d_out, int out_size)
{
    const float* hidden = (const float*)d_in[0];
    const float* cosb   = (const float*)d_in[1];
    const float* sinb   = (const float*)d_in[2];
    const float* Wq     = (const float*)d_in[3];
    const float* bq     = (const float*)d_in[4];
    const float* Wk     = (const float*)d_in[5];
    const float* bk     = (const float*)d_in[6];
    const float* Wv     = (const float*)d_in[7];
    const float* bv     = (const float*)d_in[8];
    const float* Wo     = (const float*)d_in[9];
    const float* lng    = (const float*)d_in[10];
    const float* lnb    = (const float*)d_in[11];
    float* out = (float*)d_out;

    dim3 gg(DMc / 64, BSc / 128);   // (12, 64)

    gemm_mma<<<gg, 256>>>(hidden, Wq, bq, cosb, sinb, nullptr, 0);
    gemm_mma<<<gg, 256>>>(hidden, Wk, bk, cosb, sinb, nullptr, 1);
    gemm_mma<<<gg, 256>>>(hidden, Wv, bv, cosb, sinb, nullptr, 2);

    const int flash_smem = (128 * 68 + 2 * 64 * 68 + 2 * 64 * 72) * (int)sizeof(float);
    cudaFuncSetAttribute(flash_mma,
                         cudaFuncAttributeMaxDynamicSharedMemorySize, flash_smem);
    flash_mma<<<dim3(Sc / 128, BHc), 256, flash_smem>>>();

    gemm_mma<<<gg, 256>>>(hidden, Wo, nullptr, cosb, sinb, hidden, 3);
    ln_kernel<<<BSc, 256>>>(lng, lnb, out);
}